// round 14
// baseline (speedup 1.0000x reference)
#include <cuda_runtime.h>
#include <cuda_fp16.h>

#define NN 50000
#define NE 800000
#define NG 256
#define IND 128
#define HID 64
#define EMB 128

// ---------------- scratch (device globals; no allocation) ----------------
__device__ int g_src[NE];
__device__ int g_dst[NE];
__device__ int g_batch[NN];
__device__ int g_is64_edge;
__device__ int g_is64_batch;

__device__ int g_cntn[NN];       // edge count per dst node
__device__ int g_rowptr[NN + 1]; // CSR row pointers
__device__ int g_bsum[256];      // scan block sums
__device__ int g_boff[256];      // scan block offsets
__device__ int g_cursor[NN];     // scatter cursors

struct __align__(8) Edge { int s; float c; };
__device__ Edge g_es[NE];        // dst-sorted (src, coef) pairs

__device__ float g_deg[NN];
__device__ float g_dis[NN];
// h stored as half2 (col pairs 2l,2l+1): halves gather traffic; math stays fp32
__device__ alignas(16) __half2 g_h1h[(size_t)NN * 32];  // x @ W1 (half storage)
__device__ alignas(16) __half2 g_hrh[(size_t)NN * 32];  // relu(A*h1 + b1)
__device__ alignas(16) float g_agg2[(size_t)NN * HID];  // A * hr (fp32 for gemm2)
__device__ alignas(16) float g_pool[NG * EMB];
__device__ float g_cnt[NG];

// vector f32 reduction (sm_90+)
__device__ __forceinline__ void red_add_v4(float* p, float a, float b, float c, float d) {
    asm volatile("red.global.add.v4.f32 [%0], {%1,%2,%3,%4};"
                 :: "l"(p), "f"(a), "f"(b), "f"(c), "f"(d) : "memory");
}

__device__ __forceinline__ unsigned f2tf32(float f) {
    unsigned u;
    asm("cvt.rna.tf32.f32 %0, %1;" : "=r"(u) : "f"(f));
    return u;
}

__device__ __forceinline__ void mma_tf32(float& c0, float& c1, float& c2, float& c3,
                                         unsigned a0, unsigned a1, unsigned a2, unsigned a3,
                                         unsigned b0, unsigned b1) {
    asm("mma.sync.aligned.m16n8k8.row.col.f32.tf32.tf32.f32 "
        "{%0,%1,%2,%3}, {%4,%5,%6,%7}, {%8,%9}, {%0,%1,%2,%3};"
        : "+f"(c0), "+f"(c1), "+f"(c2), "+f"(c3)
        : "r"(a0), "r"(a1), "r"(a2), "r"(a3), "r"(b0), "r"(b1));
}

// ---------------- dtype probe (parallel) ----------------
__global__ void k_detect(const void* ei, const void* batch) {
    __shared__ int se, sb;
    if (threadIdx.x == 0) { se = 1; sb = 1; }
    __syncthreads();
    int t = threadIdx.x;  // 1024 threads
    if (((const int*)ei)[2 * t + 1] != 0) se = 0;
    if (((const int*)batch)[2 * t + 1] != 0) sb = 0;
    __syncthreads();
    if (t == 0) { g_is64_edge = se; g_is64_batch = sb; }
}

// ---------------- init: deg=1 (self loop), counters/pool = 0 ----------------
__global__ void k_init() {
    int i = blockIdx.x * blockDim.x + threadIdx.x;
    if (i < NN) {
        g_deg[i] = 1.0f;
        g_cntn[i] = 0;
    }
    if (i < NG * EMB) g_pool[i] = 0.0f;
    if (i < NG) g_cnt[i] = 0.0f;
}

// convert edges + histogram (count per dst) + weighted degree, one pass
__global__ void k_cvt_edge(const void* ei, const float* __restrict__ ew) {
    int e = blockIdx.x * blockDim.x + threadIdx.x;
    if (e >= NE) return;
    int s, d;
    if (g_is64_edge) {
        const long long* p = (const long long*)ei;
        s = (int)p[e];
        d = (int)p[NE + e];
    } else {
        const int* p = (const int*)ei;
        s = p[e];
        d = p[NE + e];
    }
    g_src[e] = s;
    g_dst[e] = d;
    atomicAdd(&g_cntn[d], 1);
    atomicAdd(&g_deg[d], ew[e]);
}

// convert batch + per-graph node count (warp-aggregated atomics)
__global__ void k_cvt_batch(const void* batch) {
    int i = blockIdx.x * blockDim.x + threadIdx.x;
    if (i >= NN) return;
    int b;
    if (g_is64_batch) b = (int)((const long long*)batch)[i];
    else              b = ((const int*)batch)[i];
    g_batch[i] = b;
    unsigned mask = __match_any_sync(__activemask(), b);
    int leader = __ffs(mask) - 1;
    if ((threadIdx.x & 31) == leader)
        atomicAdd(&g_cnt[b], (float)__popc(mask));
}

// ---------------- 3-pass exclusive scan of g_cntn -> g_rowptr ----------------
__global__ void k_scan1() {
    __shared__ int sm[256];
    int t = threadIdx.x;
    int i = blockIdx.x * 256 + t;
    int v = (i < NN) ? g_cntn[i] : 0;
    sm[t] = v;
    __syncthreads();
#pragma unroll
    for (int off = 1; off < 256; off <<= 1) {
        int add = (t >= off) ? sm[t - off] : 0;
        __syncthreads();
        sm[t] += add;
        __syncthreads();
    }
    if (i < NN) g_rowptr[i] = sm[t] - v;  // exclusive
    if (t == 255) g_bsum[blockIdx.x] = sm[255];
}

__global__ void k_scan2(int nblk) {
    __shared__ int sm[256];
    int t = threadIdx.x;
    int v = (t < nblk) ? g_bsum[t] : 0;
    sm[t] = v;
    __syncthreads();
#pragma unroll
    for (int off = 1; off < 256; off <<= 1) {
        int add = (t >= off) ? sm[t - off] : 0;
        __syncthreads();
        sm[t] += add;
        __syncthreads();
    }
    if (t < nblk) g_boff[t] = sm[t] - v;  // exclusive
    if (t == 0) g_rowptr[NN] = NE;
}

// finalize rowptr/cursor + dis = rsqrt(deg) (fused)
__global__ void k_scan3() {
    int i = blockIdx.x * blockDim.x + threadIdx.x;
    if (i < NN) {
        int r = g_rowptr[i] + g_boff[i >> 8];
        g_rowptr[i] = r;
        g_cursor[i] = r;
        float d = g_deg[i];
        g_dis[i] = d > 0.0f ? rsqrtf(d) : 0.0f;
    }
}

// scatter edges into dst-sorted order with precomputed coefficient (one ST.64)
__global__ void k_scatter(const float* __restrict__ ew) {
    int e = blockIdx.x * blockDim.x + threadIdx.x;
    if (e >= NE) return;
    int s = g_src[e];
    int d = g_dst[e];
    int pos = atomicAdd(&g_cursor[d], 1);
    Edge out;
    out.s = s;
    out.c = g_dis[s] * ew[e] * g_dis[d];
    g_es[pos] = out;
}

// ---------------- tf32 tensor-core GEMM: C[n,OUT] = A[n,IN] @ W[IN,OUT] -----
// Warp computes 16 nodes x OUT via m16n8k8 mma (NN % 16 == 0 -> no ragged).
// Smem holds tf32-converted, k-permuted operands: within each 8-k block,
// k -> 2*(k&3) + ((k>>2)&1), so every fragment pair is one LDS.64:
//   A frags: (a0,a2)=[row g], (a1,a3)=[row g+8]; B frags: (b0,b1)=[col n].
// EPI=1: store half2 colpairs (c0,c1 ARE cols 2q,2q+1) to g_h1h.
// EPI=2: stage C to smem (reuse A slab), relu(+bias), v4-RED into g_pool.
template <int IN, int OUT, int EPI>
__device__ __forceinline__ void gemm_mma(const float* __restrict__ A,
                                         const float* __restrict__ W,
                                         const float* __restrict__ bias) {
    constexpr int INP = IN + 2;                  // row pad (even, 8B-align safe)
    constexpr int NT = OUT / 8;                  // n-tiles per warp
    constexpr int KS = IN / 8;                   // k-steps
    constexpr int SLAB = (16 * INP > 16 * OUT) ? 16 * INP : 16 * OUT;
    extern __shared__ unsigned smx[];
    unsigned* Wst = smx;                                          // [OUT][INP]
    unsigned* xs = smx + OUT * INP + (threadIdx.x >> 5) * SLAB;   // per-warp

    // stage W: transpose to [n][k], tf32, k-permuted
    for (int i = threadIdx.x; i < IN * OUT; i += 256) {
        int k = i / OUT, n = i % OUT;
        int kp = (k & ~7) + 2 * (k & 3) + ((k >> 2) & 1);
        Wst[n * INP + kp] = f2tf32(W[i]);
    }

    const int warp = threadIdx.x >> 5;
    const int lane = threadIdx.x & 31;
    const int n0 = (blockIdx.x * 8 + warp) * 16;

    // stage A slab: 16 nodes x IN, tf32, k-permuted (warp-local)
    if (n0 < NN) {
#pragma unroll
        for (int it = 0; it < IN / 8; it++) {
            int idx = it * 32 + lane;
            int node = idx / (IN / 4);
            int j = idx % (IN / 4);
            float4 v = *(const float4*)(A + (size_t)(n0 + node) * IN + 4 * j);
            int base8 = (4 * j) & ~7;
            int off = (j & 1);   // (4j>>2)&1
            unsigned* p = xs + node * INP + base8 + off;
            p[0] = f2tf32(v.x); p[2] = f2tf32(v.y);
            p[4] = f2tf32(v.z); p[6] = f2tf32(v.w);
        }
    }
    __syncthreads();
    if (n0 >= NN) return;

    const int g = lane >> 2, q = lane & 3;
    float c[NT][4];
#pragma unroll
    for (int nt = 0; nt < NT; nt++)
#pragma unroll
        for (int j = 0; j < 4; j++) c[nt][j] = 0.0f;

    for (int s = 0; s < KS; s++) {
        int kb = 8 * s + 2 * q;
        unsigned long long pa = *(const unsigned long long*)(xs + g * INP + kb);
        unsigned long long pb = *(const unsigned long long*)(xs + (g + 8) * INP + kb);
        unsigned a0 = (unsigned)pa, a2 = (unsigned)(pa >> 32);
        unsigned a1 = (unsigned)pb, a3 = (unsigned)(pb >> 32);
#pragma unroll
        for (int nt = 0; nt < NT; nt++) {
            unsigned long long pw =
                *(const unsigned long long*)(Wst + (nt * 8 + g) * INP + kb);
            mma_tf32(c[nt][0], c[nt][1], c[nt][2], c[nt][3],
                     a0, a1, a2, a3, (unsigned)pw, (unsigned)(pw >> 32));
        }
    }

    if (EPI == 1) {
        // c0,c1 = node g cols (2q, 2q+1); c2,c3 = node g+8 -> direct half2
#pragma unroll
        for (int nt = 0; nt < NT; nt++) {
            int cp = nt * 4 + q;
            g_h1h[(size_t)(n0 + g) * 32 + cp] = __floats2half2_rn(c[nt][0], c[nt][1]);
            g_h1h[(size_t)(n0 + g + 8) * 32 + cp] = __floats2half2_rn(c[nt][2], c[nt][3]);
        }
    } else {
        float* stg = (float*)xs;  // A slab no longer needed
#pragma unroll
        for (int nt = 0; nt < NT; nt++) {
            int col = nt * 8 + 2 * q;
            stg[g * OUT + col] = c[nt][0];
            stg[g * OUT + col + 1] = c[nt][1];
            stg[(g + 8) * OUT + col] = c[nt][2];
            stg[(g + 8) * OUT + col + 1] = c[nt][3];
        }
        __syncwarp();
        float4 b = ((const float4*)bias)[lane];
#pragma unroll 4
        for (int r = 0; r < 16; r++) {
            float4 v = *(const float4*)(stg + r * OUT + 4 * lane);
            v.x = fmaxf(v.x + b.x, 0.0f);
            v.y = fmaxf(v.y + b.y, 0.0f);
            v.z = fmaxf(v.z + b.z, 0.0f);
            v.w = fmaxf(v.w + b.w, 0.0f);
            int gr = g_batch[n0 + r];
            red_add_v4(g_pool + gr * EMB + 4 * lane, v.x, v.y, v.z, v.w);
        }
    }
}

__global__ void __launch_bounds__(256) k_gemm1(const float* __restrict__ x,
                                               const float* __restrict__ W1) {
    gemm_mma<IND, HID, 1>(x, W1, nullptr);
}
// gemm2 + bias + relu + global mean-pool accumulate (no h2 materialization)
__global__ void __launch_bounds__(256) k_gemm2pool(const float* __restrict__ W2,
                                                   const float* __restrict__ b2) {
    gemm_mma<HID, EMB, 2>(g_agg2, W2, b2);
}

// smem sizes (bytes) for the two instantiations
#define SM1 ((HID * (IND + 2) + 8 * 16 * (IND + 2)) * 4)                  // 99840
#define SM2 ((EMB * (HID + 2) + 8 * ((16 * (HID + 2) > 16 * EMB) ? 16 * (HID + 2) : 16 * EMB)) * 4)  // 99328

// ---------------- CSR aggregation, warp per dst node, half2 gathers ---------
// out[i,:] = f( dis[i]^2 * H[i,:] + sum_e coef[e]*H[src[e],:] ), fp32 math.
// OUTHALF: write half2 to g_hrh (with bias+relu); else fp32 float2 to g_agg2.
template <bool OUTHALF>
__device__ __forceinline__ void agg_body(const __half2* __restrict__ H,
                                         const float* __restrict__ bias) {
    int node = (blockIdx.x * blockDim.x + threadIdx.x) >> 5;
    int lane = threadIdx.x & 31;
    if (node >= NN) return;

    int start = g_rowptr[node];
    int end = g_rowptr[node + 1];

    float s = g_dis[node];
    s *= s;
    float2 h = __half22float2(H[(size_t)node * 32 + lane]);
    float2 acc = {s * h.x, s * h.y};

    int k = start;
    int n4 = start + ((end - start) & ~3);
    for (; k < n4; k += 4) {
        Edge e0 = g_es[k], e1 = g_es[k + 1], e2 = g_es[k + 2], e3 = g_es[k + 3];
        float2 h0 = __half22float2(H[(size_t)e0.s * 32 + lane]);
        float2 h1 = __half22float2(H[(size_t)e1.s * 32 + lane]);
        float2 h2 = __half22float2(H[(size_t)e2.s * 32 + lane]);
        float2 h3 = __half22float2(H[(size_t)e3.s * 32 + lane]);
        acc.x = fmaf(e0.c, h0.x, acc.x); acc.y = fmaf(e0.c, h0.y, acc.y);
        acc.x = fmaf(e1.c, h1.x, acc.x); acc.y = fmaf(e1.c, h1.y, acc.y);
        acc.x = fmaf(e2.c, h2.x, acc.x); acc.y = fmaf(e2.c, h2.y, acc.y);
        acc.x = fmaf(e3.c, h3.x, acc.x); acc.y = fmaf(e3.c, h3.y, acc.y);
    }
    for (; k < end; k++) {
        Edge e = g_es[k];
        float2 hh = __half22float2(H[(size_t)e.s * 32 + lane]);
        acc.x = fmaf(e.c, hh.x, acc.x);
        acc.y = fmaf(e.c, hh.y, acc.y);
    }

    if (OUTHALF) {
        float2 b = ((const float2*)bias)[lane];  // cols 2l, 2l+1
        acc.x = fmaxf(acc.x + b.x, 0.0f);
        acc.y = fmaxf(acc.y + b.y, 0.0f);
        g_hrh[(size_t)node * 32 + lane] = __float22half2_rn(acc);
    } else {
        ((float2*)g_agg2)[(size_t)node * 32 + lane] = acc;
    }
}

__global__ void k_agg1(const float* __restrict__ b1) {
    agg_body<true>(g_h1h, b1);        // g_hrh = half(relu(A*h1 + b1))
}
__global__ void k_agg2() {
    agg_body<false>(g_hrh, nullptr);  // g_agg2 = A*hr (fp32)
}

// ---------------- mean divide ----------------
__global__ void k_div(float* __restrict__ out) {
    int gid = blockIdx.x * blockDim.x + threadIdx.x;
    if (gid < NG * EMB) out[gid] = g_pool[gid] / fmaxf(g_cnt[gid >> 7], 1.0f);
}

// ---------------- launch ----------------
extern "C" void kernel_launch(void* const* d_in, const int* in_sizes, int n_in,
                              void* d_out, int out_size) {
    const float* x     = (const float*)d_in[0];
    const void*  ei    = d_in[1];  // [2, NE] int32 or int64 — probed on device
    const float* ew    = (const float*)d_in[2];
    const void*  batch = d_in[3];
    const float* W1    = (const float*)d_in[4];
    const float* b1    = (const float*)d_in[5];
    const float* W2    = (const float*)d_in[6];
    const float* b2    = (const float*)d_in[7];
    float*       out   = (float*)d_out;

    const int T = 256;
    const int NBLK = (NN + 255) / 256;            // 196
    const int GBLK = (NN / 16 + 7) / 8;           // 391 (16 nodes/warp, 8 warps)

    cudaFuncSetAttribute(k_gemm1, cudaFuncAttributeMaxDynamicSharedMemorySize, SM1);
    cudaFuncSetAttribute(k_gemm2pool, cudaFuncAttributeMaxDynamicSharedMemorySize, SM2);

    k_detect<<<1, 1024>>>(ei, batch);
    k_init<<<NBLK, T>>>();
    k_cvt_edge<<<(NE + T - 1) / T, T>>>(ei, ew);
    k_cvt_batch<<<NBLK, T>>>(batch);

    // CSR build
    k_scan1<<<NBLK, 256>>>();
    k_scan2<<<1, 256>>>(NBLK);
    k_scan3<<<NBLK, T>>>();
    k_scatter<<<(NE + T - 1) / T, T>>>(ew);

    // layer 1: h1 = half(x@W1) ; hr = half(relu(A*h1 + b1))
    k_gemm1<<<GBLK, T, SM1>>>(x, W1);
    k_agg1<<<(NN * 32 + T - 1) / T, T>>>(b1);

    // layer 2: agg2 = A*hr (fp32) ; pool += relu(agg2@W2 + b2)
    k_agg2<<<(NN * 32 + T - 1) / T, T>>>();
    k_gemm2pool<<<GBLK, T, SM2>>>(W2, b2);

    // mean
    k_div<<<(NG * EMB + T - 1) / T, T>>>(out);
}

// round 15
// speedup vs baseline: 1.0872x; 1.0872x over previous
#include <cuda_runtime.h>
#include <cuda_fp16.h>

#define NN 50000
#define NE 800000
#define NG 256
#define IND 128
#define HID 64
#define EMB 128

// ---------------- scratch (device globals; no allocation) ----------------
__device__ int g_batch[NN];
__device__ int g_is64_edge;
__device__ int g_is64_batch;

__device__ alignas(8) float2 g_degcnt[NN];  // {weighted degree, edge count}
__device__ int g_rowptr[NN + 1];            // CSR row pointers
__device__ int g_bsum[256];                 // scan block sums
__device__ int g_boff[256];                 // scan block offsets
__device__ int g_cursor[NN];                // scatter cursors

struct __align__(8) Edge { int s; float c; };
__device__ Edge g_es[NE];        // dst-sorted (src, coef) pairs

__device__ float g_dis[NN];
// h stored as half2 (col pairs 2l,2l+1): halves gather traffic; math stays fp32
__device__ alignas(16) __half2 g_h1h[(size_t)NN * 32];   // x @ W1
__device__ alignas(16) __half2 g_hrh[(size_t)NN * 32];   // relu(A*h1 + b1)
__device__ alignas(16) __half2 g_agg2h[(size_t)NN * 32]; // A * hr (half storage)
__device__ alignas(16) float g_pool[NG * EMB];
__device__ float g_cnt[NG];

// vector f32 reductions (sm_90+)
__device__ __forceinline__ void red_add_v4(float* p, float a, float b, float c, float d) {
    asm volatile("red.global.add.v4.f32 [%0], {%1,%2,%3,%4};"
                 :: "l"(p), "f"(a), "f"(b), "f"(c), "f"(d) : "memory");
}
__device__ __forceinline__ void red_add_v2(float2* p, float a, float b) {
    asm volatile("red.global.add.v2.f32 [%0], {%1,%2};"
                 :: "l"(p), "f"(a), "f"(b) : "memory");
}

// ---------------- init (deg=1, cnt=0, pool=0) + dtype probe (block 0) -------
__global__ void k_init(const void* ei, const void* batch) {
    if (blockIdx.x == 0) {
        __shared__ int se, sb;
        if (threadIdx.x == 0) { se = 1; sb = 1; }
        __syncthreads();
        // 256 threads x 4 checks: int32 edge data (uniform [0,50000)) or sorted
        // batch (reaches >=1 quickly) fails this with overwhelming probability.
        for (int k = threadIdx.x; k < 1024; k += 256) {
            if (((const int*)ei)[2 * k + 1] != 0) se = 0;
            if (((const int*)batch)[2 * k + 1] != 0) sb = 0;
        }
        __syncthreads();
        if (threadIdx.x == 0) { g_is64_edge = se; g_is64_batch = sb; }
    }
    int i = blockIdx.x * blockDim.x + threadIdx.x;
    if (i < NN) g_degcnt[i] = make_float2(1.0f, 0.0f);  // self-loop weight 1
    if (i < NG * EMB) g_pool[i] = 0.0f;
    if (i < NG) g_cnt[i] = 0.0f;
}

// per-dst weighted degree + edge count: ONE v2 RED per edge
__global__ void k_cvt_edge(const void* ei, const float* __restrict__ ew) {
    int e = blockIdx.x * blockDim.x + threadIdx.x;
    if (e >= NE) return;
    int d;
    if (g_is64_edge) d = (int)((const long long*)ei)[NE + e];
    else             d = ((const int*)ei)[NE + e];
    red_add_v2(&g_degcnt[d], ew[e], 1.0f);
}

// convert batch + per-graph node count (warp-aggregated atomics)
__global__ void k_cvt_batch(const void* batch) {
    int i = blockIdx.x * blockDim.x + threadIdx.x;
    if (i >= NN) return;
    int b;
    if (g_is64_batch) b = (int)((const long long*)batch)[i];
    else              b = ((const int*)batch)[i];
    g_batch[i] = b;
    unsigned mask = __match_any_sync(__activemask(), b);
    int leader = __ffs(mask) - 1;
    if ((threadIdx.x & 31) == leader)
        atomicAdd(&g_cnt[b], (float)__popc(mask));
}

// ---------------- 3-pass exclusive scan of edge counts -> g_rowptr ----------
__global__ void k_scan1() {
    __shared__ int sm[256];
    int t = threadIdx.x;
    int i = blockIdx.x * 256 + t;
    int v = (i < NN) ? (int)g_degcnt[i].y : 0;
    sm[t] = v;
    __syncthreads();
#pragma unroll
    for (int off = 1; off < 256; off <<= 1) {
        int add = (t >= off) ? sm[t - off] : 0;
        __syncthreads();
        sm[t] += add;
        __syncthreads();
    }
    if (i < NN) g_rowptr[i] = sm[t] - v;  // exclusive
    if (t == 255) g_bsum[blockIdx.x] = sm[255];
}

__global__ void k_scan2(int nblk) {
    __shared__ int sm[256];
    int t = threadIdx.x;
    int v = (t < nblk) ? g_bsum[t] : 0;
    sm[t] = v;
    __syncthreads();
#pragma unroll
    for (int off = 1; off < 256; off <<= 1) {
        int add = (t >= off) ? sm[t - off] : 0;
        __syncthreads();
        sm[t] += add;
        __syncthreads();
    }
    if (t < nblk) g_boff[t] = sm[t] - v;  // exclusive
    if (t == 0) g_rowptr[NN] = NE;
}

// finalize rowptr/cursor + dis = rsqrt(deg) (fused)
__global__ void k_scan3() {
    int i = blockIdx.x * blockDim.x + threadIdx.x;
    if (i < NN) {
        int r = g_rowptr[i] + g_boff[i >> 8];
        g_rowptr[i] = r;
        g_cursor[i] = r;
        float d = g_degcnt[i].x;
        g_dis[i] = d > 0.0f ? rsqrtf(d) : 0.0f;
    }
}

// scatter edges into dst-sorted order with precomputed coefficient (one ST.64)
__global__ void k_scatter(const void* ei, const float* __restrict__ ew) {
    int e = blockIdx.x * blockDim.x + threadIdx.x;
    if (e >= NE) return;
    int s, d;
    if (g_is64_edge) {
        const long long* p = (const long long*)ei;
        s = (int)p[e];
        d = (int)p[NE + e];
    } else {
        const int* p = (const int*)ei;
        s = p[e];
        d = p[NE + e];
    }
    int pos = atomicAdd(&g_cursor[d], 1);
    Edge out;
    out.s = s;
    out.c = g_dis[s] * ew[e] * g_dis[d];
    g_es[pos] = out;
}

// ---------------- f32x2 register-tiled GEMM ---------------------------------
// C = A @ W. kk-paired u64 accumulators; LDS.64 operands (xs pairs + transposed
// Wst pairs); lane owns interleaved cols {lane, lane+32, ...}.
// AHALF: A rows stored as __half (converted to fp32 at stage-in).
// EPI=1: regroup cols via smem, convert to half2, store to g_h1h.
// EPI=2: regroup cols via smem, relu(+bias), v4-RED into g_pool (mean pool).
template <int IN, int OUT, int EPI, bool AHALF>
__device__ __forceinline__ void gemm_f32x2(const void* __restrict__ A,
                                           const float* __restrict__ W,
                                           const float* __restrict__ bias) {
    constexpr int MT = 8;
    constexpr int VEC = OUT / 32;     // 2 (OUT=64) or 4 (OUT=128)
    constexpr int INP = IN + 2;       // pad: 2-phase-safe LDS.64 banks
    constexpr int KB = 32;
    __shared__ __align__(16) float Wst[OUT * INP];   // W transposed [col][k]
    __shared__ __align__(16) float xs[8][MT][KB];
    __shared__ __align__(16) float stg[8][OUT];

    for (int i = threadIdx.x; i < IN * OUT; i += blockDim.x) {
        int k = i / OUT, c = i % OUT;
        Wst[c * INP + k] = W[i];
    }
    __syncthreads();

    const int warp = threadIdx.x >> 5;
    const int lane = threadIdx.x & 31;
    const int n0 = (blockIdx.x * 8 + warp) * MT;
    if (n0 >= NN) return;

    unsigned long long acc[MT][VEC];
#pragma unroll
    for (int m = 0; m < MT; m++)
#pragma unroll
        for (int c = 0; c < VEC; c++) acc[m][c] = 0ULL;

    for (int kb = 0; kb < IN; kb += KB) {
#pragma unroll
        for (int m = 0; m < MT; m++) {
            float v = 0.0f;
            if (n0 + m < NN) {
                if (AHALF)
                    v = __half2float(((const __half*)A)[(size_t)(n0 + m) * IN + kb + lane]);
                else
                    v = ((const float*)A)[(size_t)(n0 + m) * IN + kb + lane];
            }
            xs[warp][m][lane] = v;
        }
        __syncwarp();
#pragma unroll
        for (int t = 0; t < KB / 2; t++) {
            unsigned long long xp[MT];
#pragma unroll
            for (int m = 0; m < MT; m++)
                xp[m] = *(const unsigned long long*)&xs[warp][m][2 * t];
            unsigned long long wp[VEC];
#pragma unroll
            for (int c = 0; c < VEC; c++)
                wp[c] = *(const unsigned long long*)&Wst[(lane + 32 * c) * INP + kb + 2 * t];
#pragma unroll
            for (int m = 0; m < MT; m++)
#pragma unroll
                for (int c = 0; c < VEC; c++)
                    asm("fma.rn.f32x2 %0, %1, %2, %0;"
                        : "+l"(acc[m][c]) : "l"(xp[m]), "l"(wp[c]));
        }
        __syncwarp();
    }

#pragma unroll
    for (int m = 0; m < MT; m++) {
        int n = n0 + m;
        if (n >= NN) break;  // uniform across warp
        float val[VEC];
#pragma unroll
        for (int c = 0; c < VEC; c++) {
            float lo = __uint_as_float((unsigned)acc[m][c]);
            float hi = __uint_as_float((unsigned)(acc[m][c] >> 32));
            val[c] = lo + hi;
        }
#pragma unroll
        for (int c = 0; c < VEC; c++) stg[warp][lane + 32 * c] = val[c];
        __syncwarp();
        if (EPI == 1) {
            float2 v = *(const float2*)&stg[warp][2 * lane];  // cols 2l, 2l+1
            g_h1h[(size_t)n * 32 + lane] = __float22half2_rn(v);
        } else {
            float4 v = *(const float4*)&stg[warp][4 * lane];
            float4 b = ((const float4*)bias)[lane];
            v.x = fmaxf(v.x + b.x, 0.0f);
            v.y = fmaxf(v.y + b.y, 0.0f);
            v.z = fmaxf(v.z + b.z, 0.0f);
            v.w = fmaxf(v.w + b.w, 0.0f);
            int g = g_batch[n];
            red_add_v4(g_pool + g * EMB + 4 * lane, v.x, v.y, v.z, v.w);
        }
        __syncwarp();
    }
}

__global__ void __launch_bounds__(256) k_gemm1(const float* __restrict__ x,
                                               const float* __restrict__ W1) {
    gemm_f32x2<IND, HID, 1, false>(x, W1, nullptr);
}
// gemm2 + bias + relu + global mean-pool accumulate (no h2 materialization)
__global__ void __launch_bounds__(256) k_gemm2pool(const float* __restrict__ W2,
                                                   const float* __restrict__ b2) {
    gemm_f32x2<HID, EMB, 2, true>(g_agg2h, W2, b2);
}

// ---------------- CSR aggregation, warp per dst node, half2 gathers ---------
// out[i,:] = f( dis[i]^2 * H[i,:] + sum_e coef[e]*H[src[e],:] ), fp32 math.
// BIASRELU: +bias, relu. Output always half2.
template <bool BIASRELU>
__device__ __forceinline__ void agg_body(const __half2* __restrict__ H,
                                         const float* __restrict__ bias,
                                         __half2* __restrict__ O) {
    int node = (blockIdx.x * blockDim.x + threadIdx.x) >> 5;
    int lane = threadIdx.x & 31;
    if (node >= NN) return;

    int start = g_rowptr[node];
    int end = g_rowptr[node + 1];

    float s = g_dis[node];
    s *= s;
    float2 h = __half22float2(H[(size_t)node * 32 + lane]);
    float2 acc = {s * h.x, s * h.y};

    int k = start;
    int n4 = start + ((end - start) & ~3);
    for (; k < n4; k += 4) {
        Edge e0 = g_es[k], e1 = g_es[k + 1], e2 = g_es[k + 2], e3 = g_es[k + 3];
        float2 h0 = __half22float2(H[(size_t)e0.s * 32 + lane]);
        float2 h1 = __half22float2(H[(size_t)e1.s * 32 + lane]);
        float2 h2 = __half22float2(H[(size_t)e2.s * 32 + lane]);
        float2 h3 = __half22float2(H[(size_t)e3.s * 32 + lane]);
        acc.x = fmaf(e0.c, h0.x, acc.x); acc.y = fmaf(e0.c, h0.y, acc.y);
        acc.x = fmaf(e1.c, h1.x, acc.x); acc.y = fmaf(e1.c, h1.y, acc.y);
        acc.x = fmaf(e2.c, h2.x, acc.x); acc.y = fmaf(e2.c, h2.y, acc.y);
        acc.x = fmaf(e3.c, h3.x, acc.x); acc.y = fmaf(e3.c, h3.y, acc.y);
    }
    for (; k < end; k++) {
        Edge e = g_es[k];
        float2 hh = __half22float2(H[(size_t)e.s * 32 + lane]);
        acc.x = fmaf(e.c, hh.x, acc.x);
        acc.y = fmaf(e.c, hh.y, acc.y);
    }

    if (BIASRELU) {
        float2 b = ((const float2*)bias)[lane];  // cols 2l, 2l+1
        acc.x = fmaxf(acc.x + b.x, 0.0f);
        acc.y = fmaxf(acc.y + b.y, 0.0f);
    }
    O[(size_t)node * 32 + lane] = __float22half2_rn(acc);
}

__global__ void k_agg1(const float* __restrict__ b1) {
    agg_body<true>(g_h1h, b1, g_hrh);        // hr = half(relu(A*h1 + b1))
}
__global__ void k_agg2() {
    agg_body<false>(g_hrh, nullptr, g_agg2h);  // agg2 = half(A*hr)
}

// ---------------- mean divide ----------------
__global__ void k_div(float* __restrict__ out) {
    int gid = blockIdx.x * blockDim.x + threadIdx.x;
    if (gid < NG * EMB) out[gid] = g_pool[gid] / fmaxf(g_cnt[gid >> 7], 1.0f);
}

// ---------------- launch ----------------
extern "C" void kernel_launch(void* const* d_in, const int* in_sizes, int n_in,
                              void* d_out, int out_size) {
    const float* x     = (const float*)d_in[0];
    const void*  ei    = d_in[1];  // [2, NE] int32 or int64 — probed on device
    const float* ew    = (const float*)d_in[2];
    const void*  batch = d_in[3];
    const float* W1    = (const float*)d_in[4];
    const float* b1    = (const float*)d_in[5];
    const float* W2    = (const float*)d_in[6];
    const float* b2    = (const float*)d_in[7];
    float*       out   = (float*)d_out;

    const int T = 256;
    const int NBLK = (NN + 255) / 256;            // 196
    const int GBLK = (NN + 63) / 64;              // 8 nodes/warp * 8 warps

    k_init<<<NBLK, T>>>(ei, batch);               // init + dtype probe
    k_cvt_edge<<<(NE + T - 1) / T, T>>>(ei, ew);
    k_cvt_batch<<<NBLK, T>>>(batch);

    // CSR build
    k_scan1<<<NBLK, 256>>>();
    k_scan2<<<1, 256>>>(NBLK);
    k_scan3<<<NBLK, T>>>();
    k_scatter<<<(NE + T - 1) / T, T>>>(ei, ew);

    // layer 1: h1 = half(x@W1) ; hr = half(relu(A*h1 + b1))
    k_gemm1<<<GBLK, T>>>(x, W1);
    k_agg1<<<(NN * 32 + T - 1) / T, T>>>(b1);

    // layer 2: agg2 = half(A*hr) ; pool += relu(agg2@W2 + b2)
    k_agg2<<<(NN * 32 + T - 1) / T, T>>>();
    k_gemm2pool<<<GBLK, T>>>(W2, b2);

    // mean
    k_div<<<(NG * EMB + T - 1) / T, T>>>(out);
}

// round 16
// speedup vs baseline: 1.1282x; 1.0378x over previous
#include <cuda_runtime.h>
#include <cuda_fp16.h>

#define NN 50000
#define NE 800000
#define NG 256
#define IND 128
#define HID 64
#define EMB 128

// ---------------- scratch (device globals; no allocation) -------------------
// INVARIANT: every accumulator below is zero at kernel_launch entry; each call
// re-zeroes what it dirties (module-load zero-init makes call 1 clean).
__device__ int g_batch[NN];
__device__ alignas(8) float2 g_degcnt[NN];       // {sum ew, edge count} (zeroed by scan)
__device__ unsigned long long g_scanstate[256];  // lookback words (zeroed by divclean)
__device__ int g_rowptr[NN + 1];                 // CSR row pointers
__device__ int g_cursor[NN];                     // scatter cursors

struct __align__(8) Edge { int s; float c; };
__device__ Edge g_es[NE];        // dst-sorted (src, coef) pairs

__device__ float g_dis[NN];
// h stored as half2 (col pairs 2l,2l+1): halves gather traffic; math stays fp32
__device__ alignas(16) __half2 g_h1h[(size_t)NN * 32];   // x @ W1
__device__ alignas(16) __half2 g_hrh[(size_t)NN * 32];   // relu(A*h1 + b1)
__device__ alignas(16) __half2 g_agg2h[(size_t)NN * 32]; // A * hr (half storage)
__device__ alignas(16) float g_pool[NG * EMB];           // zeroed by divclean
__device__ float g_cnt[NG];                              // zeroed by divclean

// vector f32 reductions (sm_90+)
__device__ __forceinline__ void red_add_v4(float* p, float a, float b, float c, float d) {
    asm volatile("red.global.add.v4.f32 [%0], {%1,%2,%3,%4};"
                 :: "l"(p), "f"(a), "f"(b), "f"(c), "f"(d) : "memory");
}
__device__ __forceinline__ void red_add_v2(float2* p, float a, float b) {
    asm volatile("red.global.add.v2.f32 [%0], {%1,%2};"
                 :: "l"(p), "f"(a), "f"(b) : "memory");
}

// ---------------- inline dtype probes (thread 0 + smem broadcast) -----------
// int64 values < 2^31 have zero odd 32-bit words. Probe positions are in-bounds
// and nonzero-w.h.p. under BOTH interpretations.
__device__ __forceinline__ int probe_edge64(const void* ei) {
    const int* w = (const int*)ei;
    int e64 = 1;
#pragma unroll
    for (int k = 0; k < 8; k++)
        if (w[2 * (k * (NE / 8)) + 1] != 0) e64 = 0;  // uniform [0,50000) if i32
    return e64;
}
__device__ __forceinline__ int probe_batch64(const void* batch) {
    const int* w = (const int*)batch;
    int b64 = 1;
#pragma unroll
    for (int k = 0; k < 8; k++)
        if (w[2 * (10000 + k * 1500) + 1] != 0) b64 = 0;  // i32 idx 20001..41001: graph ~100+
    return b64;
}

// ---------------- edge histogram/degree + batch convert (fused) -------------
__global__ void k_cvt(const void* ei, const float* __restrict__ ew, const void* batch) {
    __shared__ int s_e64, s_b64;
    if (threadIdx.x == 0) { s_e64 = probe_edge64(ei); s_b64 = probe_batch64(batch); }
    __syncthreads();
    int e = blockIdx.x * 256 + threadIdx.x;
    if (e < NE) {
        int d = s_e64 ? (int)((const long long*)ei)[NE + e] : ((const int*)ei)[NE + e];
        red_add_v2(&g_degcnt[d], ew[e], 1.0f);   // one v2 RED: {deg+=w, cnt+=1}
    }
    if (e < NN) {
        int b = s_b64 ? (int)((const long long*)batch)[e] : ((const int*)batch)[e];
        g_batch[e] = b;
        unsigned mask = __match_any_sync(__activemask(), b);
        int leader = __ffs(mask) - 1;
        if ((threadIdx.x & 31) == leader)
            atomicAdd(&g_cnt[b], (float)__popc(mask));
    }
}

// ---------------- single-kernel scan (decoupled lookback) + finalize --------
// state word: bits[63:62] 0=empty 1=aggregate 2=inclusive; low 32 = value.
__global__ void k_scanall() {
    __shared__ int sm[256];
    __shared__ int s_off;
    int t = threadIdx.x, b = blockIdx.x;
    int i = b * 256 + t;
    int v = (i < NN) ? (int)g_degcnt[i].y : 0;
    sm[t] = v;
    __syncthreads();
#pragma unroll
    for (int off = 1; off < 256; off <<= 1) {
        int add = (t >= off) ? sm[t - off] : 0;
        __syncthreads();
        sm[t] += add;
        __syncthreads();
    }
    int total = sm[255];

    if (t == 0) {
        unsigned long long w = ((b == 0 ? 2ULL : 1ULL) << 62) | (unsigned)total;
        atomicExch(&g_scanstate[b], w);
        if (b == 0) s_off = 0;
    }
    if (b > 0 && t < 32) {   // warp 0: parallel lookback
        int offset = 0;
        int base = b - 1;
        for (;;) {
            int idx = base - t;
            unsigned long long w = 0;
            if (idx >= 0) {
                do { w = *(volatile unsigned long long*)&g_scanstate[idx]; }
                while ((w >> 62) == 0);
            }
            unsigned inclm = __ballot_sync(0xffffffffu, idx >= 0 && (w >> 62) == 2ULL);
            int stop = inclm ? (__ffs(inclm) - 1) : 32;
            int val = (idx >= 0 && t <= stop) ? (int)(unsigned)w : 0;
#pragma unroll
            for (int o = 16; o; o >>= 1) val += __shfl_xor_sync(0xffffffffu, val, o);
            offset += val;
            if (inclm) break;
            base -= 32;     // unreachable past block 0 (always inclusive)
        }
        if (t == 0) {
            s_off = offset;
            atomicExch(&g_scanstate[b], (2ULL << 62) | (unsigned)(offset + total));
        }
    }
    __syncthreads();

    if (i < NN) {
        int r = s_off + sm[t] - v;   // exclusive prefix
        g_rowptr[i] = r;
        g_cursor[i] = r;
        g_dis[i] = rsqrtf(1.0f + g_degcnt[i].x);   // self-loop weight 1 analytic
        g_degcnt[i] = make_float2(0.0f, 0.0f);     // clean for next call
        if (i == NN - 1) g_rowptr[NN] = NE;
    }
}

// scatter edges into dst-sorted order with precomputed coefficient (one ST.64)
__global__ void k_scatter(const void* ei, const float* __restrict__ ew) {
    __shared__ int s_e64;
    if (threadIdx.x == 0) s_e64 = probe_edge64(ei);
    __syncthreads();
    int e = blockIdx.x * 256 + threadIdx.x;
    if (e >= NE) return;
    int s, d;
    if (s_e64) {
        const long long* p = (const long long*)ei;
        s = (int)p[e];
        d = (int)p[NE + e];
    } else {
        const int* p = (const int*)ei;
        s = p[e];
        d = p[NE + e];
    }
    int pos = atomicAdd(&g_cursor[d], 1);
    Edge out;
    out.s = s;
    out.c = g_dis[s] * ew[e] * g_dis[d];
    g_es[pos] = out;
}

// ---------------- f32x2 register-tiled GEMM ---------------------------------
// C = A @ W. kk-paired u64 accumulators; LDS.64 operands (xs pairs + transposed
// Wst pairs); lane owns interleaved cols {lane, lane+32, ...}.
// AHALF: A rows stored as __half. EPI=1: half2 colpairs -> g_h1h.
// EPI=2: regroup via smem, relu(+bias), v4-RED into g_pool (mean pool).
template <int IN, int OUT, int EPI, bool AHALF>
__device__ __forceinline__ void gemm_f32x2(const void* __restrict__ A,
                                           const float* __restrict__ W,
                                           const float* __restrict__ bias) {
    constexpr int MT = 8;
    constexpr int VEC = OUT / 32;
    constexpr int INP = IN + 2;
    constexpr int KB = 32;
    __shared__ __align__(16) float Wst[OUT * INP];
    __shared__ __align__(16) float xs[8][MT][KB];
    __shared__ __align__(16) float stg[8][OUT];

    for (int i = threadIdx.x; i < IN * OUT; i += blockDim.x) {
        int k = i / OUT, c = i % OUT;
        Wst[c * INP + k] = W[i];
    }
    __syncthreads();

    const int warp = threadIdx.x >> 5;
    const int lane = threadIdx.x & 31;
    const int n0 = (blockIdx.x * 8 + warp) * MT;
    if (n0 >= NN) return;

    unsigned long long acc[MT][VEC];
#pragma unroll
    for (int m = 0; m < MT; m++)
#pragma unroll
        for (int c = 0; c < VEC; c++) acc[m][c] = 0ULL;

    for (int kb = 0; kb < IN; kb += KB) {
#pragma unroll
        for (int m = 0; m < MT; m++) {
            float v = 0.0f;
            if (n0 + m < NN) {
                if (AHALF)
                    v = __half2float(((const __half*)A)[(size_t)(n0 + m) * IN + kb + lane]);
                else
                    v = ((const float*)A)[(size_t)(n0 + m) * IN + kb + lane];
            }
            xs[warp][m][lane] = v;
        }
        __syncwarp();
#pragma unroll
        for (int t = 0; t < KB / 2; t++) {
            unsigned long long xp[MT];
#pragma unroll
            for (int m = 0; m < MT; m++)
                xp[m] = *(const unsigned long long*)&xs[warp][m][2 * t];
            unsigned long long wp[VEC];
#pragma unroll
            for (int c = 0; c < VEC; c++)
                wp[c] = *(const unsigned long long*)&Wst[(lane + 32 * c) * INP + kb + 2 * t];
#pragma unroll
            for (int m = 0; m < MT; m++)
#pragma unroll
                for (int c = 0; c < VEC; c++)
                    asm("fma.rn.f32x2 %0, %1, %2, %0;"
                        : "+l"(acc[m][c]) : "l"(xp[m]), "l"(wp[c]));
        }
        __syncwarp();
    }

#pragma unroll
    for (int m = 0; m < MT; m++) {
        int n = n0 + m;
        if (n >= NN) break;  // uniform across warp
        float val[VEC];
#pragma unroll
        for (int c = 0; c < VEC; c++) {
            float lo = __uint_as_float((unsigned)acc[m][c]);
            float hi = __uint_as_float((unsigned)(acc[m][c] >> 32));
            val[c] = lo + hi;
        }
#pragma unroll
        for (int c = 0; c < VEC; c++) stg[warp][lane + 32 * c] = val[c];
        __syncwarp();
        if (EPI == 1) {
            float2 v = *(const float2*)&stg[warp][2 * lane];  // cols 2l, 2l+1
            g_h1h[(size_t)n * 32 + lane] = __float22half2_rn(v);
        } else {
            float4 v = *(const float4*)&stg[warp][4 * lane];
            float4 b = ((const float4*)bias)[lane];
            v.x = fmaxf(v.x + b.x, 0.0f);
            v.y = fmaxf(v.y + b.y, 0.0f);
            v.z = fmaxf(v.z + b.z, 0.0f);
            v.w = fmaxf(v.w + b.w, 0.0f);
            int g = g_batch[n];
            red_add_v4(g_pool + g * EMB + 4 * lane, v.x, v.y, v.z, v.w);
        }
        __syncwarp();
    }
}

__global__ void __launch_bounds__(256) k_gemm1(const float* __restrict__ x,
                                               const float* __restrict__ W1) {
    gemm_f32x2<IND, HID, 1, false>(x, W1, nullptr);
}
__global__ void __launch_bounds__(256) k_gemm2pool(const float* __restrict__ W2,
                                                   const float* __restrict__ b2) {
    gemm_f32x2<HID, EMB, 2, true>(g_agg2h, W2, b2);
}

// ---------------- CSR aggregation, warp per dst node, half2 gathers ---------
template <bool BIASRELU>
__device__ __forceinline__ void agg_body(const __half2* __restrict__ H,
                                         const float* __restrict__ bias,
                                         __half2* __restrict__ O) {
    int node = (blockIdx.x * blockDim.x + threadIdx.x) >> 5;
    int lane = threadIdx.x & 31;
    if (node >= NN) return;

    int start = g_rowptr[node];
    int end = g_rowptr[node + 1];

    float s = g_dis[node];
    s *= s;
    float2 h = __half22float2(H[(size_t)node * 32 + lane]);
    float2 acc = {s * h.x, s * h.y};

    int k = start;
    int n4 = start + ((end - start) & ~3);
    for (; k < n4; k += 4) {
        Edge e0 = g_es[k], e1 = g_es[k + 1], e2 = g_es[k + 2], e3 = g_es[k + 3];
        float2 h0 = __half22float2(H[(size_t)e0.s * 32 + lane]);
        float2 h1 = __half22float2(H[(size_t)e1.s * 32 + lane]);
        float2 h2 = __half22float2(H[(size_t)e2.s * 32 + lane]);
        float2 h3 = __half22float2(H[(size_t)e3.s * 32 + lane]);
        acc.x = fmaf(e0.c, h0.x, acc.x); acc.y = fmaf(e0.c, h0.y, acc.y);
        acc.x = fmaf(e1.c, h1.x, acc.x); acc.y = fmaf(e1.c, h1.y, acc.y);
        acc.x = fmaf(e2.c, h2.x, acc.x); acc.y = fmaf(e2.c, h2.y, acc.y);
        acc.x = fmaf(e3.c, h3.x, acc.x); acc.y = fmaf(e3.c, h3.y, acc.y);
    }
    for (; k < end; k++) {
        Edge e = g_es[k];
        float2 hh = __half22float2(H[(size_t)e.s * 32 + lane]);
        acc.x = fmaf(e.c, hh.x, acc.x);
        acc.y = fmaf(e.c, hh.y, acc.y);
    }

    if (BIASRELU) {
        float2 b = ((const float2*)bias)[lane];
        acc.x = fmaxf(acc.x + b.x, 0.0f);
        acc.y = fmaxf(acc.y + b.y, 0.0f);
    }
    O[(size_t)node * 32 + lane] = __float22half2_rn(acc);
}

__global__ void k_agg1(const float* __restrict__ b1) {
    agg_body<true>(g_h1h, b1, g_hrh);
}
__global__ void k_agg2() {
    agg_body<false>(g_hrh, nullptr, g_agg2h);
}

// ---------------- mean divide + state cleanup for next call -----------------
// grid = exactly 128 blocks x 256 (NG*EMB). cnt[g]'s readers (gids g*128..)
// live in one block -> block-local sync makes read-then-zero race-free.
__global__ void k_divclean(float* __restrict__ out) {
    int gid = blockIdx.x * 256 + threadIdx.x;
    float c = fmaxf(g_cnt[gid >> 7], 1.0f);
    out[gid] = g_pool[gid] / c;
    g_pool[gid] = 0.0f;
    __syncthreads();
    if (threadIdx.x < 2) g_cnt[blockIdx.x * 2 + threadIdx.x] = 0.0f;
    if (blockIdx.x == 0) g_scanstate[threadIdx.x] = 0ULL;
}

// ---------------- launch ----------------
extern "C" void kernel_launch(void* const* d_in, const int* in_sizes, int n_in,
                              void* d_out, int out_size) {
    const float* x     = (const float*)d_in[0];
    const void*  ei    = d_in[1];  // [2, NE] int32 or int64 — probed on device
    const float* ew    = (const float*)d_in[2];
    const void*  batch = d_in[3];
    const float* W1    = (const float*)d_in[4];
    const float* b1    = (const float*)d_in[5];
    const float* W2    = (const float*)d_in[6];
    const float* b2    = (const float*)d_in[7];
    float*       out   = (float*)d_out;

    const int T = 256;
    const int NBLK = (NN + 255) / 256;    // 196
    const int GBLK = (NN + 63) / 64;      // 782 (8 nodes/warp * 8 warps)

    // CSR build (3 kernels)
    k_cvt<<<(NE + T - 1) / T, T>>>(ei, ew, batch);
    k_scanall<<<NBLK, 256>>>();
    k_scatter<<<(NE + T - 1) / T, T>>>(ei, ew);

    // layer 1: h1 = half(x@W1) ; hr = half(relu(A*h1 + b1))
    k_gemm1<<<GBLK, T>>>(x, W1);
    k_agg1<<<(NN * 32 + T - 1) / T, T>>>(b1);

    // layer 2: agg2 = half(A*hr) ; pool += relu(agg2@W2 + b2)
    k_agg2<<<(NN * 32 + T - 1) / T, T>>>();
    k_gemm2pool<<<GBLK, T>>>(W2, b2);

    // mean + cleanup (leaves all accumulators zero for next call)
    k_divclean<<<(NG * EMB) / T, T>>>(out);
}